// round 2
// baseline (speedup 1.0000x reference)
#include <cuda_runtime.h>
#include <math.h>

// Problem constants
#define BB 2
#define CC_TOT 64      // output channels / neighbour channels
#define HH 256
#define WW 256
#define KK9 9
#define DG 8
#define CG 8           // C / DG
#define NOFF 144       // 2*KK*DG
#define NMSK 72        // KK*DG
#define NCONV 216      // NOFF + NMSK
#define CIN 128        // 2*C

// Scratch: [B][216][H][W]: channels 0..143 offsets, 144..215 sigmoided mask
__device__ float g_offmask[(size_t)BB * NCONV * HH * WW];

// ---------------------------------------------------------------------------
// Kernel 1: 3x3 conv (pad 1) of concat(ref, neighbour) -> offset (144ch) and
// sigmoid(mask) (72ch). Tile: 8 rows x 64 cols per block, 128 threads.
// Each thread: 4 consecutive cols x 12 output channels (48 accumulators).
// grid: (W/64=4, H/8=32, B*18=36)  — blockIdx.z encodes (batch, out-chunk).
// ---------------------------------------------------------------------------
__global__ void __launch_bounds__(128)
conv_offmask_kernel(const float* __restrict__ ref,
                    const float* __restrict__ nbr,
                    const float* __restrict__ off_w,
                    const float* __restrict__ off_b,
                    const float* __restrict__ mask_w,
                    const float* __restrict__ mask_b)
{
    const int TW = 64, TH = 8, CCH = 8, OC = 12;

    const int w0 = blockIdx.x * TW;
    const int h0 = blockIdx.y * TH;
    const int bz = blockIdx.z;
    const int b = bz / 18;
    const int chunk = bz % 18;
    const bool isMask = (chunk >= 12);
    const int oBase = isMask ? (chunk - 12) * OC : chunk * OC;
    const float* wsrc = isMask ? mask_w : off_w;
    const float* bsrc = isMask ? mask_b : off_b;

    __shared__ float s_in[CCH][TH + 2][68];   // 66 cols used, stride 68
    __shared__ float s_w[OC][CCH][9];

    const int tid = threadIdx.x;
    const int r = tid >> 4;            // row within tile 0..7
    const int cb = (tid & 15) * 4;     // col base within tile 0..60

    float acc[4][OC];
#pragma unroll
    for (int p = 0; p < 4; p++)
#pragma unroll
        for (int o = 0; o < OC; o++) acc[p][o] = 0.f;

#pragma unroll 1
    for (int icc = 0; icc < CIN / CCH; icc++) {
        __syncthreads();
        // stage input tile: 8 channels x 10 rows x 66 cols (zero-padded halo)
        for (int idx = tid; idx < CCH * 10 * 66; idx += 128) {
            int c   = idx / (10 * 66);
            int rem = idx % (10 * 66);
            int rr  = rem / 66;
            int xx  = rem % 66;
            int y = h0 - 1 + rr;
            int x = w0 - 1 + xx;
            int gc = icc * CCH + c;                 // global input channel 0..127
            const float* src = (gc < CC_TOT) ? ref : nbr;
            int ch = gc & (CC_TOT - 1);
            float v = 0.f;
            if (y >= 0 && y < HH && x >= 0 && x < WW)
                v = src[((size_t)(b * CC_TOT + ch) * HH + y) * WW + x];
            s_in[c][rr][xx] = v;
        }
        // stage weights: 12 out x 8 in x 9
        for (int idx = tid; idx < OC * CCH * 9; idx += 128) {
            int o   = idx / (CCH * 9);
            int rem = idx % (CCH * 9);
            int c = rem / 9;
            int k = rem % 9;
            s_w[o][c][k] = wsrc[((size_t)(oBase + o) * CIN + icc * CCH + c) * 9 + k];
        }
        __syncthreads();

#pragma unroll 1
        for (int c = 0; c < CCH; c++) {
#pragma unroll
            for (int ky = 0; ky < 3; ky++) {
                float2 v01 = *(const float2*)&s_in[c][r + ky][cb];
                float2 v23 = *(const float2*)&s_in[c][r + ky][cb + 2];
                float2 v45 = *(const float2*)&s_in[c][r + ky][cb + 4];
                float iv[6] = {v01.x, v01.y, v23.x, v23.y, v45.x, v45.y};
#pragma unroll
                for (int kx = 0; kx < 3; kx++) {
#pragma unroll
                    for (int o = 0; o < OC; o++) {
                        float wv = s_w[o][c][ky * 3 + kx];
#pragma unroll
                        for (int p = 0; p < 4; p++)
                            acc[p][o] = fmaf(iv[p + kx], wv, acc[p][o]);
                    }
                }
            }
        }
    }

    // epilogue: bias (+ sigmoid for mask channels), store float4 per channel
    const int h = h0 + r;
#pragma unroll
    for (int o = 0; o < OC; o++) {
        float bv = bsrc[oBase + o];
        int ogl = isMask ? (NOFF + oBase + o) : (oBase + o);
        float4 v;
        v.x = acc[0][o] + bv;
        v.y = acc[1][o] + bv;
        v.z = acc[2][o] + bv;
        v.w = acc[3][o] + bv;
        if (isMask) {
            v.x = 1.f / (1.f + __expf(-v.x));
            v.y = 1.f / (1.f + __expf(-v.y));
            v.z = 1.f / (1.f + __expf(-v.z));
            v.w = 1.f / (1.f + __expf(-v.w));
        }
        *(float4*)&g_offmask[((size_t)(b * NCONV + ogl) * HH + h) * WW + w0 + cb] = v;
    }
}

// ---------------------------------------------------------------------------
// Kernel 2: bilinear deform-sample * mask into smem (im2col column of 576 per
// pixel), then per-pixel GEMM 576 -> 64 output channels.
// Tile: 16 pixels along W. Block: 128 threads.
// grid: (W/16=16, H=256, B=2)
// ---------------------------------------------------------------------------
__global__ void __launch_bounds__(128)
deform_gemm_kernel(const float* __restrict__ nbr,
                   const float* __restrict__ weight,
                   const float* __restrict__ bias,
                   float* __restrict__ out)
{
    __shared__ float s_samp[16][580];   // [px][(g*8+c)*9+k], stride 580 (conflict-free)

    const int tid = threadIdx.x;
    const int b  = blockIdx.z;
    const int h  = blockIdx.y;
    const int w0 = blockIdx.x * 16;

    // ---- Phase A: sample ----
    {
        const int px = tid & 15;
        const int g  = tid >> 4;     // 0..7
        const int w  = w0 + px;
        const float* om  = g_offmask + (size_t)b * NCONV * HH * WW;
        const float* img = nbr + (size_t)(b * CC_TOT + g * CG) * HH * WW;

#pragma unroll 1
        for (int k = 0; k < KK9; k++) {
            int ky = k / 3, kx = k % 3;
            float dy = om[((size_t)(g * 18 + 2 * k)     * HH + h) * WW + w];
            float dx = om[((size_t)(g * 18 + 2 * k + 1) * HH + h) * WW + w];
            float m  = om[((size_t)(NOFF + g * KK9 + k) * HH + h) * WW + w];
            float y = (float)(h - 1 + ky) + dy;
            float x = (float)(w - 1 + kx) + dx;
            float y0f = floorf(y), x0f = floorf(x);
            float wy = y - y0f, wx = x - x0f;
            int y0 = (int)y0f, x0 = (int)x0f;
            int y1 = y0 + 1, x1 = x0 + 1;
            float vy0 = (y0 >= 0 && y0 < HH) ? 1.f : 0.f;
            float vy1 = (y1 >= 0 && y1 < HH) ? 1.f : 0.f;
            float vx0 = (x0 >= 0 && x0 < WW) ? 1.f : 0.f;
            float vx1 = (x1 >= 0 && x1 < WW) ? 1.f : 0.f;
            float w00 = (1.f - wy) * (1.f - wx) * vy0 * vx0 * m;
            float w01 = (1.f - wy) * wx         * vy0 * vx1 * m;
            float w10 = wy         * (1.f - wx) * vy1 * vx0 * m;
            float w11 = wy         * wx         * vy1 * vx1 * m;
            int yc0 = min(max(y0, 0), HH - 1);
            int yc1 = min(max(y1, 0), HH - 1);
            int xc0 = min(max(x0, 0), WW - 1);
            int xc1 = min(max(x1, 0), WW - 1);
            int i00 = yc0 * WW + xc0;
            int i01 = yc0 * WW + xc1;
            int i10 = yc1 * WW + xc0;
            int i11 = yc1 * WW + xc1;
#pragma unroll
            for (int c = 0; c < CG; c++) {
                const float* ip = img + (size_t)c * HH * WW;
                float s = w00 * ip[i00] + w01 * ip[i01] + w10 * ip[i10] + w11 * ip[i11];
                s_samp[px][(g * CG + c) * KK9 + k] = s;
            }
        }
    }
    __syncthreads();

    // ---- Phase B: GEMM 16px x 64out, K=576 ----
    {
        const int pp = tid & 7;          // px pair: {pp, pp+8}
        const int oq = tid >> 3;         // 0..15 -> outs oq*4..+3
        const float* wbase = weight + (size_t)oq * 4 * 576;

        float acc0[4] = {0.f, 0.f, 0.f, 0.f};
        float acc1[4] = {0.f, 0.f, 0.f, 0.f};

#pragma unroll 4
        for (int kk = 0; kk < 576; kk += 4) {
            float4 s0 = *(const float4*)&s_samp[pp][kk];
            float4 s1 = *(const float4*)&s_samp[pp + 8][kk];
#pragma unroll
            for (int j = 0; j < 4; j++) {
                float4 wv = *(const float4*)&wbase[(size_t)j * 576 + kk];
                acc0[j] = fmaf(s0.x, wv.x, acc0[j]);
                acc0[j] = fmaf(s0.y, wv.y, acc0[j]);
                acc0[j] = fmaf(s0.z, wv.z, acc0[j]);
                acc0[j] = fmaf(s0.w, wv.w, acc0[j]);
                acc1[j] = fmaf(s1.x, wv.x, acc1[j]);
                acc1[j] = fmaf(s1.y, wv.y, acc1[j]);
                acc1[j] = fmaf(s1.z, wv.z, acc1[j]);
                acc1[j] = fmaf(s1.w, wv.w, acc1[j]);
            }
        }

#pragma unroll
        for (int j = 0; j < 4; j++) {
            int o = oq * 4 + j;
            float bv = bias[o];
            size_t base = ((size_t)(b * CC_TOT + o) * HH + h) * WW + w0;
            out[base + pp]     = acc0[j] + bv;
            out[base + pp + 8] = acc1[j] + bv;
        }
    }
}

extern "C" void kernel_launch(void* const* d_in, const int* in_sizes, int n_in,
                              void* d_out, int out_size)
{
    const float* ref     = (const float*)d_in[0];
    const float* nbr     = (const float*)d_in[1];
    const float* off_w   = (const float*)d_in[2];
    const float* off_b   = (const float*)d_in[3];
    const float* mask_w  = (const float*)d_in[4];
    const float* mask_b  = (const float*)d_in[5];
    const float* weight  = (const float*)d_in[6];
    const float* bias    = (const float*)d_in[7];
    float* out = (float*)d_out;

    dim3 g1(WW / 64, HH / 8, BB * 18);
    conv_offmask_kernel<<<g1, 128>>>(ref, nbr, off_w, off_b, mask_w, mask_b);

    dim3 g2(WW / 16, HH, BB);
    deform_gemm_kernel<<<g2, 128>>>(nbr, weight, bias, out);
}

// round 4
// speedup vs baseline: 1.3540x; 1.3540x over previous
#include <cuda_runtime.h>
#include <math.h>
#include <cstdint>

// Problem constants
#define BB 2
#define CC_TOT 64      // output channels / neighbour channels
#define HH 256
#define WW 256
#define KK9 9
#define DG 8
#define CG 8           // C / DG
#define NOFF 144       // 2*KK*DG
#define NMSK 72        // KK*DG
#define NCONV 216      // NOFF + NMSK
#define CIN 128        // 2*C
#define NCH 16         // K chunks (8 input channels each)
#define KCH 72         // K per chunk (8 ch * 9 taps)
#define OCP 224        // padded out channels (216 -> 224)

typedef unsigned int u32;

// Scratch: [B][216][H][W]: channels 0..143 offsets, 144..215 sigmoided mask
__device__ float g_offmask[(size_t)BB * NCONV * HH * WW];
// Packed conv weights: [chunk][k=c*9+tap][och(padded 224)], tf32-rounded
__device__ float g_wpack[(size_t)NCH * KCH * OCP];

static __device__ __forceinline__ u32 f2tf32(float v) {
    u32 t;
    asm("cvt.rna.tf32.f32 %0, %1;" : "=r"(t) : "f"(v));
    return t;
}

// ---------------------------------------------------------------------------
// Kernel 0: pack weights into [chunk][k][och] layout (tf32-rounded).
// ---------------------------------------------------------------------------
__global__ void pack_weights_kernel(const float* __restrict__ off_w,
                                    const float* __restrict__ mask_w)
{
    int n = blockIdx.x * blockDim.x + threadIdx.x;
    if (n >= NCH * KCH * OCP) return;
    int oc = n % OCP;
    int k  = (n / OCP) % KCH;
    int cc = n / (OCP * KCH);
    int c   = k / 9;
    int tap = k - 9 * c;
    float v = 0.f;
    if (oc < NOFF)
        v = off_w[((size_t)oc * CIN + cc * 8 + c) * 9 + tap];
    else if (oc < NCONV)
        v = mask_w[((size_t)(oc - NOFF) * CIN + cc * 8 + c) * 9 + tap];
    g_wpack[n] = __uint_as_float(f2tf32(v));
}

// ---------------------------------------------------------------------------
// Kernel 1: 3x3 conv via tf32 mma.sync implicit GEMM.
// Block: 256 threads (8 warps), tile = 128 pixels (along W) x 112 out-ch.
// grid.x = 1024 pixel tiles (b,h,half-row), grid.y = 2 och chunks.
// Warp layout: pg = wid&3 (32-px slice), og = wid>>2 (56-och slice).
// ---------------------------------------------------------------------------
__global__ void __launch_bounds__(256, 2)
conv_mma_kernel(const float* __restrict__ ref,
                const float* __restrict__ nbr,
                const float* __restrict__ off_b,
                const float* __restrict__ mask_b)
{
    extern __shared__ float smem[];
    float (*s_col)[136] = (float(*)[136])smem;               // [72][128] px-contig
    float (*s_w)[120]   = (float(*)[120])(smem + KCH * 136); // [72][112] och-contig

    const int tid = threadIdx.x;
    const int wid = tid >> 5;
    const int lane = tid & 31;
    const int gid = lane >> 2;   // groupID 0..7
    const int tig = lane & 3;    // 0..3
    const int pg = wid & 3;      // pixel group (32 px)
    const int og = wid >> 2;     // och group (56 och)

    const int tile = blockIdx.x;
    const int w0 = (tile & 1) * 128;
    const int h  = (tile >> 1) & 255;
    const int b  = tile >> 9;
    const int ocChunk = blockIdx.y;           // 0 or 1 -> och base 0 / 112

    float acc[2][7][4];
#pragma unroll
    for (int pt = 0; pt < 2; pt++)
#pragma unroll
        for (int nt = 0; nt < 7; nt++)
#pragma unroll
            for (int j = 0; j < 4; j++) acc[pt][nt][j] = 0.f;

#pragma unroll 1
    for (int cc = 0; cc < NCH; cc++) {
        __syncthreads();
        // ---- build im2col chunk: s_col[k][px], k = c*9 + tap, 72x128 ----
#pragma unroll 1
        for (int i = 0; i < 36; i++) {
            int idx = i * 256 + tid;
            int k  = idx >> 7;
            int px = idx & 127;
            int c   = k / 9;
            int tap = k - 9 * c;
            int ky = tap / 3;
            int kx = tap - 3 * ky;
            int y = h + ky - 1;
            int x = w0 + px + kx - 1;
            int gc = cc * 8 + c;
            const float* src = (gc < CC_TOT) ? ref : nbr;
            int ch = gc & (CC_TOT - 1);
            float v = 0.f;
            if (y >= 0 && y < HH && x >= 0 && x < WW)
                v = src[((size_t)(b * CC_TOT + ch) * HH + y) * WW + x];
            s_col[k][px] = __uint_as_float(f2tf32(v));
        }
        // ---- stage weights: s_w[k][oc], 72x112, coalesced from g_wpack ----
        {
            const float* wp = g_wpack + (size_t)cc * KCH * OCP + ocChunk * 112;
            for (int idx = tid; idx < KCH * 112; idx += 256) {
                int k  = idx / 112;
                int oc = idx - 112 * k;
                s_w[k][oc] = wp[(size_t)k * OCP + oc];
            }
        }
        __syncthreads();

        // ---- mma: 9 k-tiles of 8 ----
#pragma unroll
        for (int kt = 0; kt < 9; kt++) {
            const int kb = kt * 8;
            u32 afr[2][4];
#pragma unroll
            for (int pt = 0; pt < 2; pt++) {
                int r0 = pg * 32 + pt * 16 + gid;
                afr[pt][0] = __float_as_uint(s_col[kb + tig][r0]);
                afr[pt][1] = __float_as_uint(s_col[kb + tig][r0 + 8]);
                afr[pt][2] = __float_as_uint(s_col[kb + tig + 4][r0]);
                afr[pt][3] = __float_as_uint(s_col[kb + tig + 4][r0 + 8]);
            }
#pragma unroll
            for (int nt = 0; nt < 7; nt++) {
                int ocw = og * 56 + nt * 8 + gid;
                u32 b0 = __float_as_uint(s_w[kb + tig][ocw]);
                u32 b1 = __float_as_uint(s_w[kb + tig + 4][ocw]);
#pragma unroll
                for (int pt = 0; pt < 2; pt++) {
                    asm volatile(
                        "mma.sync.aligned.m16n8k8.row.col.f32.tf32.tf32.f32 "
                        "{%0,%1,%2,%3}, {%4,%5,%6,%7}, {%8,%9}, {%0,%1,%2,%3};"
                        : "+f"(acc[pt][nt][0]), "+f"(acc[pt][nt][1]),
                          "+f"(acc[pt][nt][2]), "+f"(acc[pt][nt][3])
                        : "r"(afr[pt][0]), "r"(afr[pt][1]),
                          "r"(afr[pt][2]), "r"(afr[pt][3]),
                          "r"(b0), "r"(b1));
                }
            }
        }
    }

    // ---- epilogue: bias (+ sigmoid for mask channels), write g_offmask ----
#pragma unroll
    for (int pt = 0; pt < 2; pt++) {
#pragma unroll
        for (int nt = 0; nt < 7; nt++) {
            int pxb = pg * 32 + pt * 16 + gid;
            int o2  = ocChunk * 112 + og * 56 + nt * 8 + tig * 2;
#pragma unroll
            for (int j = 0; j < 4; j++) {
                int och = o2 + (j & 1);
                int px  = pxb + (j >> 1) * 8;
                if (och < NCONV) {
                    float bv = (och < NOFF) ? off_b[och] : mask_b[och - NOFF];
                    float v = acc[pt][nt][j] + bv;
                    if (och >= NOFF) v = 1.f / (1.f + __expf(-v));
                    g_offmask[((size_t)(b * NCONV + och) * HH + h) * WW + w0 + px] = v;
                }
            }
        }
    }
}

// ---------------------------------------------------------------------------
// Kernel 2: bilinear deform-sample * mask into smem (im2col column of 576 per
// pixel), then per-pixel GEMM 576 -> 64 output channels. (unchanged from R2)
// ---------------------------------------------------------------------------
__global__ void __launch_bounds__(128)
deform_gemm_kernel(const float* __restrict__ nbr,
                   const float* __restrict__ weight,
                   const float* __restrict__ bias,
                   float* __restrict__ out)
{
    __shared__ float s_samp[16][580];

    const int tid = threadIdx.x;
    const int b  = blockIdx.z;
    const int h  = blockIdx.y;
    const int w0 = blockIdx.x * 16;

    // ---- Phase A: sample ----
    {
        const int px = tid & 15;
        const int g  = tid >> 4;
        const int w  = w0 + px;
        const float* om  = g_offmask + (size_t)b * NCONV * HH * WW;
        const float* img = nbr + (size_t)(b * CC_TOT + g * CG) * HH * WW;

#pragma unroll 1
        for (int k = 0; k < KK9; k++) {
            int ky = k / 3, kx = k % 3;
            float dy = om[((size_t)(g * 18 + 2 * k)     * HH + h) * WW + w];
            float dx = om[((size_t)(g * 18 + 2 * k + 1) * HH + h) * WW + w];
            float m  = om[((size_t)(NOFF + g * KK9 + k) * HH + h) * WW + w];
            float y = (float)(h - 1 + ky) + dy;
            float x = (float)(w - 1 + kx) + dx;
            float y0f = floorf(y), x0f = floorf(x);
            float wy = y - y0f, wx = x - x0f;
            int y0 = (int)y0f, x0 = (int)x0f;
            int y1 = y0 + 1, x1 = x0 + 1;
            float vy0 = (y0 >= 0 && y0 < HH) ? 1.f : 0.f;
            float vy1 = (y1 >= 0 && y1 < HH) ? 1.f : 0.f;
            float vx0 = (x0 >= 0 && x0 < WW) ? 1.f : 0.f;
            float vx1 = (x1 >= 0 && x1 < WW) ? 1.f : 0.f;
            float w00 = (1.f - wy) * (1.f - wx) * vy0 * vx0 * m;
            float w01 = (1.f - wy) * wx         * vy0 * vx1 * m;
            float w10 = wy         * (1.f - wx) * vy1 * vx0 * m;
            float w11 = wy         * wx         * vy1 * vx1 * m;
            int yc0 = min(max(y0, 0), HH - 1);
            int yc1 = min(max(y1, 0), HH - 1);
            int xc0 = min(max(x0, 0), WW - 1);
            int xc1 = min(max(x1, 0), WW - 1);
            int i00 = yc0 * WW + xc0;
            int i01 = yc0 * WW + xc1;
            int i10 = yc1 * WW + xc0;
            int i11 = yc1 * WW + xc1;
#pragma unroll
            for (int c = 0; c < CG; c++) {
                const float* ip = img + (size_t)c * HH * WW;
                float s = w00 * ip[i00] + w01 * ip[i01] + w10 * ip[i10] + w11 * ip[i11];
                s_samp[px][(g * CG + c) * KK9 + k] = s;
            }
        }
    }
    __syncthreads();

    // ---- Phase B: GEMM 16px x 64out, K=576 ----
    {
        const int pp = tid & 7;
        const int oq = tid >> 3;
        const float* wbase = weight + (size_t)oq * 4 * 576;

        float acc0[4] = {0.f, 0.f, 0.f, 0.f};
        float acc1[4] = {0.f, 0.f, 0.f, 0.f};

#pragma unroll 4
        for (int kk = 0; kk < 576; kk += 4) {
            float4 s0 = *(const float4*)&s_samp[pp][kk];
            float4 s1 = *(const float4*)&s_samp[pp + 8][kk];
#pragma unroll
            for (int j = 0; j < 4; j++) {
                float4 wv = *(const float4*)&wbase[(size_t)j * 576 + kk];
                acc0[j] = fmaf(s0.x, wv.x, acc0[j]);
                acc0[j] = fmaf(s0.y, wv.y, acc0[j]);
                acc0[j] = fmaf(s0.z, wv.z, acc0[j]);
                acc0[j] = fmaf(s0.w, wv.w, acc0[j]);
                acc1[j] = fmaf(s1.x, wv.x, acc1[j]);
                acc1[j] = fmaf(s1.y, wv.y, acc1[j]);
                acc1[j] = fmaf(s1.z, wv.z, acc1[j]);
                acc1[j] = fmaf(s1.w, wv.w, acc1[j]);
            }
        }

#pragma unroll
        for (int j = 0; j < 4; j++) {
            int o = oq * 4 + j;
            float bv = bias[o];
            size_t base = ((size_t)(b * CC_TOT + o) * HH + h) * WW + w0;
            out[base + pp]     = acc0[j] + bv;
            out[base + pp + 8] = acc1[j] + bv;
        }
    }
}

extern "C" void kernel_launch(void* const* d_in, const int* in_sizes, int n_in,
                              void* d_out, int out_size)
{
    const float* ref     = (const float*)d_in[0];
    const float* nbr     = (const float*)d_in[1];
    const float* off_w   = (const float*)d_in[2];
    const float* off_b   = (const float*)d_in[3];
    const float* mask_w  = (const float*)d_in[4];
    const float* mask_b  = (const float*)d_in[5];
    const float* weight  = (const float*)d_in[6];
    const float* bias    = (const float*)d_in[7];
    float* out = (float*)d_out;

    // weight pre-pack (tiny)
    {
        int total = NCH * KCH * OCP;
        pack_weights_kernel<<<(total + 255) / 256, 256>>>(off_w, mask_w);
    }

    // tf32 mma conv
    {
        const int smem_bytes = (KCH * 136 + KCH * 120) * 4;   // 73728
        cudaFuncSetAttribute(conv_mma_kernel,
                             cudaFuncAttributeMaxDynamicSharedMemorySize,
                             smem_bytes);
        dim3 g1(1024, 2);
        conv_mma_kernel<<<g1, 256, smem_bytes>>>(ref, nbr, off_b, mask_b);
    }

    dim3 g2(WW / 16, HH, BB);
    deform_gemm_kernel<<<g2, 128>>>(nbr, weight, bias, out);
}